// round 11
// baseline (speedup 1.0000x reference)
#include <cuda_runtime.h>
#include <cuda_bf16.h>

// Gram-Schmidt over M=4 model outputs, per (batch, channel) vector of D=1024.
// x: [4, 128, 64, 1024] fp32, out same shape.
//
// R2:  all 10 pairwise dots G_ij in ONE fused block reduction; GS coefficients
//      are scalar algebra on G (lower-triangular T, basis_i = sum_j T_ij v_j).
// R10: 256-bit memory ops (LDG.256/STG.256), 128 thr/CTA: kernel 39.4->37.2us.
// R11: temporal pipeline across 4 pairs per CTA (grid 2048, stride gridDim):
//      pair i+1's 4 LDG.256 issue BEFORE pair i's reduction, so the DRAM pipe
//      stays fed through every reduction/finalize/store phase. Occupancy is
//      proven inert (44-68% all flat), so the reg cost (2 buffers) is free.

#define NTHREADS 128
#define D_DIM 1024
#define NPAIRS 8192              // B*C
#define GRID 2048
#define ITERS 4                  // NPAIRS / GRID
#define MSTRIDE_B 33554432u      // B*C*D*4 bytes = 32 MB

struct f8 { float4 a, b; };

__device__ __forceinline__ f8 ldg256(const void* p) {
    f8 r;
    asm("ld.global.v8.b32 {%0,%1,%2,%3,%4,%5,%6,%7}, [%8];"
        : "=f"(r.a.x), "=f"(r.a.y), "=f"(r.a.z), "=f"(r.a.w),
          "=f"(r.b.x), "=f"(r.b.y), "=f"(r.b.z), "=f"(r.b.w)
        : "l"(p));
    return r;
}

__device__ __forceinline__ void stg256(void* p, f8 v) {
    asm volatile("st.global.v8.b32 [%0], {%1,%2,%3,%4,%5,%6,%7,%8};"
                 :: "l"(p),
                    "f"(v.a.x), "f"(v.a.y), "f"(v.a.z), "f"(v.a.w),
                    "f"(v.b.x), "f"(v.b.y), "f"(v.b.z), "f"(v.b.w)
                 : "memory");
}

__device__ __forceinline__ float dot8(f8 u, f8 v) {
    return u.a.x * v.a.x + u.a.y * v.a.y + u.a.z * v.a.z + u.a.w * v.a.w +
           u.b.x * v.b.x + u.b.y * v.b.y + u.b.z * v.b.z + u.b.w * v.b.w;
}

__device__ __forceinline__ float4 comb4(float4 v0, float s0) {
    return make_float4(s0 * v0.x, s0 * v0.y, s0 * v0.z, s0 * v0.w);
}
__device__ __forceinline__ float4 comb4(float4 v0, float s0, float4 v1, float s1) {
    return make_float4(s0 * v0.x + s1 * v1.x, s0 * v0.y + s1 * v1.y,
                       s0 * v0.z + s1 * v1.z, s0 * v0.w + s1 * v1.w);
}
__device__ __forceinline__ float4 comb4(float4 v0, float s0, float4 v1, float s1,
                                        float4 v2, float s2) {
    return make_float4(s0 * v0.x + s1 * v1.x + s2 * v2.x,
                       s0 * v0.y + s1 * v1.y + s2 * v2.y,
                       s0 * v0.z + s1 * v1.z + s2 * v2.z,
                       s0 * v0.w + s1 * v1.w + s2 * v2.w);
}
__device__ __forceinline__ float4 comb4(float4 v0, float s0, float4 v1, float s1,
                                        float4 v2, float s2, float4 v3, float s3) {
    return make_float4(s0 * v0.x + s1 * v1.x + s2 * v2.x + s3 * v3.x,
                       s0 * v0.y + s1 * v1.y + s2 * v2.y + s3 * v3.y,
                       s0 * v0.z + s1 * v1.z + s2 * v2.z + s3 * v3.z,
                       s0 * v0.w + s1 * v1.w + s2 * v2.w + s3 * v3.w);
}

// Reduction + GS finalize + 4 stores for one pair (v0..v3 in registers).
__device__ __forceinline__ void process_pair(
    f8 v0, f8 v1, f8 v2, f8 v3,
    float (*red)[12], float* gsm,
    int tid, int lane, int warp,
    char* ob, unsigned base)
{
    float p[10];
    p[0] = dot8(v0, v0); p[1] = dot8(v0, v1); p[2] = dot8(v0, v2);
    p[3] = dot8(v0, v3); p[4] = dot8(v1, v1); p[5] = dot8(v1, v2);
    p[6] = dot8(v1, v3); p[7] = dot8(v2, v2); p[8] = dot8(v2, v3);
    p[9] = dot8(v3, v3);

#pragma unroll
    for (int lvl = 16; lvl >= 1; lvl >>= 1) {
#pragma unroll
        for (int q = 0; q < 5; q++) {
            unsigned long long u =
                ((unsigned long long)__float_as_uint(p[2 * q + 1]) << 32) |
                (unsigned long long)__float_as_uint(p[2 * q]);
            unsigned long long r = __shfl_xor_sync(0xffffffffu, u, lvl);
            p[2 * q]     += __uint_as_float((unsigned)r);
            p[2 * q + 1] += __uint_as_float((unsigned)(r >> 32));
        }
    }

    if (lane == 0) {
        float4* row = reinterpret_cast<float4*>(red[warp]);
        row[0] = make_float4(p[0], p[1], p[2], p[3]);
        row[1] = make_float4(p[4], p[5], p[6], p[7]);
        red[warp][8] = p[8];
        red[warp][9] = p[9];
    }
    __syncthreads();

    if (tid < 10)
        gsm[tid] = red[0][tid] + red[1][tid] + red[2][tid] + red[3][tid];
    __syncthreads();

    float4 ga = *reinterpret_cast<const float4*>(gsm);
    float4 gb = *reinterpret_cast<const float4*>(gsm + 4);
    const float g23 = gsm[8], g33 = gsm[9];
    const float g00 = ga.x, g01 = ga.y, g02 = ga.z, g03 = ga.w;
    const float g11 = gb.x, g12 = gb.y, g13 = gb.z, g22 = gb.w;

    const float inv0 = (g00 > 0.f) ? rsqrtf(g00) : 0.f;

    const float c0 = g01 * inv0;
    const float n1 = fmaxf(g11 - c0 * c0, 0.f);
    const float inv1 = (n1 > 0.f) ? rsqrtf(n1) : 0.f;
    const float T10 = -c0 * inv0 * inv1;
    const float T11 = inv1;

    const float d0 = g02 * inv0;
    const float d1 = T10 * g02 + T11 * g12;
    const float n2 = fmaxf(g22 - d0 * d0 - d1 * d1, 0.f);
    const float inv2 = (n2 > 0.f) ? rsqrtf(n2) : 0.f;
    const float T20 = inv2 * (-d0 * inv0 - d1 * T10);
    const float T21 = inv2 * (-d1 * T11);
    const float T22 = inv2;

    const float e0 = g03 * inv0;
    const float e1 = T10 * g03 + T11 * g13;
    const float e2 = T20 * g03 + T21 * g13 + T22 * g23;
    const float n3 = fmaxf(g33 - e0 * e0 - e1 * e1 - e2 * e2, 0.f);
    const float inv3 = (n3 > 0.f) ? rsqrtf(n3) : 0.f;
    const float T30 = inv3 * (-e0 * inv0 - e1 * T10 - e2 * T20);
    const float T31 = inv3 * (-e1 * T11 - e2 * T21);
    const float T32 = inv3 * (-e2 * T22);
    const float T33 = inv3;

    f8 o;
    o.a = comb4(v0.a, inv0); o.b = comb4(v0.b, inv0);
    stg256(ob + base, o);

    o.a = comb4(v0.a, T10, v1.a, T11); o.b = comb4(v0.b, T10, v1.b, T11);
    stg256(ob + base + MSTRIDE_B, o);

    o.a = comb4(v0.a, T20, v1.a, T21, v2.a, T22);
    o.b = comb4(v0.b, T20, v1.b, T21, v2.b, T22);
    stg256(ob + base + 2u * MSTRIDE_B, o);

    o.a = comb4(v0.a, T30, v1.a, T31, v2.a, T32, v3.a, T33);
    o.b = comb4(v0.b, T30, v1.b, T31, v2.b, T32, v3.b, T33);
    stg256(ob + base + 3u * MSTRIDE_B, o);
}

__global__ __launch_bounds__(NTHREADS, 4)
void gram_schmidt_kernel(const float* __restrict__ x, float* __restrict__ out) {
    const int tid  = threadIdx.x;
    const int lane = tid & 31;
    const int warp = tid >> 5;

    __shared__ float red[4][12];
    __shared__ __align__(16) float gsm[12];

    const char* xb = (const char*)x;
    char* ob = (char*)out;
    const unsigned toff = (unsigned)tid * 32u;

    // pair index strided by GRID: adjacent CTAs stay on adjacent pairs.
    unsigned base = blockIdx.x * (D_DIM * 4u) + toff;
    const unsigned step = GRID * (D_DIM * 4u);   // 8 MB

    // prologue loads (pair 0)
    f8 c0 = ldg256(xb + base);
    f8 c1 = ldg256(xb + base + MSTRIDE_B);
    f8 c2 = ldg256(xb + base + 2u * MSTRIDE_B);
    f8 c3 = ldg256(xb + base + 3u * MSTRIDE_B);

#pragma unroll
    for (int it = 0; it < ITERS; it++) {
        f8 n0, n1, n2, n3;
        const unsigned nbase = base + step;
        if (it + 1 < ITERS) {
            // prefetch next pair: in flight through this pair's reduction
            n0 = ldg256(xb + nbase);
            n1 = ldg256(xb + nbase + MSTRIDE_B);
            n2 = ldg256(xb + nbase + 2u * MSTRIDE_B);
            n3 = ldg256(xb + nbase + 3u * MSTRIDE_B);
        }

        process_pair(c0, c1, c2, c3, red, gsm, tid, lane, warp, ob, base);

        if (it + 1 < ITERS) {
            c0 = n0; c1 = n1; c2 = n2; c3 = n3;
            base = nbase;
        }
    }
}

extern "C" void kernel_launch(void* const* d_in, const int* in_sizes, int n_in,
                              void* d_out, int out_size) {
    const float* x = (const float*)d_in[0];
    float* out = (float*)d_out;
    gram_schmidt_kernel<<<GRID, NTHREADS>>>(x, out);
}

// round 13
// speedup vs baseline: 1.0119x; 1.0119x over previous
#include <cuda_runtime.h>
#include <cuda_bf16.h>
#include <cstdint>

// Gram-Schmidt over M=4 model outputs, per (batch, channel) vector of D=1024.
// x: [4, 128, 64, 1024] fp32, out same shape.
//
// R2:  all 10 pairwise dots G_ij in ONE fused block reduction; GS coefficients
//      are scalar algebra on G (lower-triangular T, basis_i = sum_j T_ij v_j).
// R10: LDG.256/STG.256, 128 thr/CTA: kernel 37.2us, DRAM 70.6%.
// R12: cp.async smem double-buffer pipeline -> WRONG RESULTS: asm ops lacked
//      "memory" clobbers, so the compiler had no ordering edge between the
//      cp.async writes and the smem reads (zeros read -> zero output).
// R13: same pipeline, airtight ordering: volatile + "memory" on every
//      cp.async op and on the LDS reads. Logic unchanged.

#define NTHREADS 128
#define D_DIM 1024
#define GRID 2048
#define ITERS 4                   // 8192 pairs / GRID
#define MSTRIDE_B 33554432u       // 32 MB between model slabs
#define PAIR_B 4096u              // bytes per (b,c) vector
#define VSTRIDE 4608u             // padded smem vector tile (4KB + 512B pad)
#define SSTRIDE (4u * VSTRIDE)    // one stage: 4 vectors = 18432 B

struct f8 { float4 a, b; };

__device__ __forceinline__ void cp16(uint32_t dst, const void* src) {
    asm volatile("cp.async.cg.shared.global [%0], [%1], 16;"
                 :: "r"(dst), "l"(src) : "memory");
}
__device__ __forceinline__ void cp_commit() {
    asm volatile("cp.async.commit_group;" ::: "memory");
}
template <int N>
__device__ __forceinline__ void cp_wait() {
    asm volatile("cp.async.wait_group %0;" :: "n"(N) : "memory");
}

__device__ __forceinline__ float4 lds128(uint32_t a) {
    float4 v;
    asm volatile("ld.shared.v4.f32 {%0,%1,%2,%3}, [%4];"
                 : "=f"(v.x), "=f"(v.y), "=f"(v.z), "=f"(v.w)
                 : "r"(a) : "memory");
    return v;
}

__device__ __forceinline__ void stg256(void* p, f8 v) {
    asm volatile("st.global.v8.b32 [%0], {%1,%2,%3,%4,%5,%6,%7,%8};"
                 :: "l"(p),
                    "f"(v.a.x), "f"(v.a.y), "f"(v.a.z), "f"(v.a.w),
                    "f"(v.b.x), "f"(v.b.y), "f"(v.b.z), "f"(v.b.w)
                 : "memory");
}

__device__ __forceinline__ float dot8(f8 u, f8 v) {
    return u.a.x * v.a.x + u.a.y * v.a.y + u.a.z * v.a.z + u.a.w * v.a.w +
           u.b.x * v.b.x + u.b.y * v.b.y + u.b.z * v.b.z + u.b.w * v.b.w;
}

__device__ __forceinline__ float4 comb4(float4 v0, float s0) {
    return make_float4(s0 * v0.x, s0 * v0.y, s0 * v0.z, s0 * v0.w);
}
__device__ __forceinline__ float4 comb4(float4 v0, float s0, float4 v1, float s1) {
    return make_float4(s0 * v0.x + s1 * v1.x, s0 * v0.y + s1 * v1.y,
                       s0 * v0.z + s1 * v1.z, s0 * v0.w + s1 * v1.w);
}
__device__ __forceinline__ float4 comb4(float4 v0, float s0, float4 v1, float s1,
                                        float4 v2, float s2) {
    return make_float4(s0 * v0.x + s1 * v1.x + s2 * v2.x,
                       s0 * v0.y + s1 * v1.y + s2 * v2.y,
                       s0 * v0.z + s1 * v1.z + s2 * v2.z,
                       s0 * v0.w + s1 * v1.w + s2 * v2.w);
}
__device__ __forceinline__ float4 comb4(float4 v0, float s0, float4 v1, float s1,
                                        float4 v2, float s2, float4 v3, float s3) {
    return make_float4(s0 * v0.x + s1 * v1.x + s2 * v2.x + s3 * v3.x,
                       s0 * v0.y + s1 * v1.y + s2 * v2.y + s3 * v3.y,
                       s0 * v0.z + s1 * v1.z + s2 * v2.z + s3 * v3.z,
                       s0 * v0.w + s1 * v1.w + s2 * v2.w + s3 * v3.w);
}

__global__ __launch_bounds__(NTHREADS, 6)
void gram_schmidt_kernel(const float* __restrict__ x, float* __restrict__ out) {
    const int tid  = threadIdx.x;
    const int lane = tid & 31;
    const int warp = tid >> 5;

    __shared__ __align__(16) char buf[2 * SSTRIDE];   // 36 KB double buffer
    __shared__ float red[4][12];
    __shared__ __align__(16) float gsm[12];

    const char* xb = (const char*)x;
    char* ob = (char*)out;

    // padded smem offset: conflict-free LDS.128 at 32B/thread granularity
    const uint32_t poff = (uint32_t)tid * 32u + ((uint32_t)(tid >> 2)) * 16u;
    const uint32_t sbase = (uint32_t)__cvta_generic_to_shared(buf);
    const unsigned goff = (unsigned)tid * 32u;

    // issue pair (blockIdx.x + it*GRID) into stage s
    auto issue = [&](int s, int it) {
        const unsigned gb = (blockIdx.x + (unsigned)it * GRID) * PAIR_B + goff;
        const uint32_t st = sbase + (uint32_t)s * SSTRIDE + poff;
#pragma unroll
        for (unsigned m = 0; m < 4; m++) {
            cp16(st + m * VSTRIDE,       xb + gb + m * MSTRIDE_B);
            cp16(st + m * VSTRIDE + 16u, xb + gb + m * MSTRIDE_B + 16u);
        }
        cp_commit();
    };

    issue(0, 0);
    issue(1, 1);

#pragma unroll
    for (int it = 0; it < ITERS; it++) {
        const int s = it & 1;
        if (it < ITERS - 1) cp_wait<1>(); else cp_wait<0>();
        __syncthreads();   // stage s visible to all threads

        // read this thread's 32B of each vector from smem
        const uint32_t st = sbase + (uint32_t)s * SSTRIDE + poff;
        f8 v0, v1, v2, v3;
        v0.a = lds128(st);                 v0.b = lds128(st + 16u);
        v1.a = lds128(st + VSTRIDE);       v1.b = lds128(st + VSTRIDE + 16u);
        v2.a = lds128(st + 2u * VSTRIDE);  v2.b = lds128(st + 2u * VSTRIDE + 16u);
        v3.a = lds128(st + 3u * VSTRIDE);  v3.b = lds128(st + 3u * VSTRIDE + 16u);

        // 10 pairwise dot partials
        float p[10];
        p[0] = dot8(v0, v0); p[1] = dot8(v0, v1); p[2] = dot8(v0, v2);
        p[3] = dot8(v0, v3); p[4] = dot8(v1, v1); p[5] = dot8(v1, v2);
        p[6] = dot8(v1, v3); p[7] = dot8(v2, v2); p[8] = dot8(v2, v3);
        p[9] = dot8(v3, v3);

        // packed warp butterfly
#pragma unroll
        for (int lvl = 16; lvl >= 1; lvl >>= 1) {
#pragma unroll
            for (int q = 0; q < 5; q++) {
                unsigned long long u =
                    ((unsigned long long)__float_as_uint(p[2 * q + 1]) << 32) |
                    (unsigned long long)__float_as_uint(p[2 * q]);
                unsigned long long r = __shfl_xor_sync(0xffffffffu, u, lvl);
                p[2 * q]     += __uint_as_float((unsigned)r);
                p[2 * q + 1] += __uint_as_float((unsigned)(r >> 32));
            }
        }
        if (lane == 0) {
            float4* row = reinterpret_cast<float4*>(red[warp]);
            row[0] = make_float4(p[0], p[1], p[2], p[3]);
            row[1] = make_float4(p[4], p[5], p[6], p[7]);
            red[warp][8] = p[8];
            red[warp][9] = p[9];
        }
        __syncthreads();   // also proves every thread finished LDS of stage s

        // refill the stage we just consumed (in flight through the rest)
        if (it + 2 < ITERS) issue(s, it + 2);

        if (tid < 10)
            gsm[tid] = red[0][tid] + red[1][tid] + red[2][tid] + red[3][tid];
        __syncthreads();

        float4 ga = *reinterpret_cast<const float4*>(gsm);
        float4 gb = *reinterpret_cast<const float4*>(gsm + 4);
        const float g23 = gsm[8], g33 = gsm[9];
        const float g00 = ga.x, g01 = ga.y, g02 = ga.z, g03 = ga.w;
        const float g11 = gb.x, g12 = gb.y, g13 = gb.z, g22 = gb.w;

        const float inv0 = (g00 > 0.f) ? rsqrtf(g00) : 0.f;

        const float c0 = g01 * inv0;
        const float n1 = fmaxf(g11 - c0 * c0, 0.f);
        const float inv1 = (n1 > 0.f) ? rsqrtf(n1) : 0.f;
        const float T10 = -c0 * inv0 * inv1;
        const float T11 = inv1;

        const float d0 = g02 * inv0;
        const float d1 = T10 * g02 + T11 * g12;
        const float n2 = fmaxf(g22 - d0 * d0 - d1 * d1, 0.f);
        const float inv2 = (n2 > 0.f) ? rsqrtf(n2) : 0.f;
        const float T20 = inv2 * (-d0 * inv0 - d1 * T10);
        const float T21 = inv2 * (-d1 * T11);
        const float T22 = inv2;

        const float e0 = g03 * inv0;
        const float e1 = T10 * g03 + T11 * g13;
        const float e2 = T20 * g03 + T21 * g13 + T22 * g23;
        const float n3 = fmaxf(g33 - e0 * e0 - e1 * e1 - e2 * e2, 0.f);
        const float inv3 = (n3 > 0.f) ? rsqrtf(n3) : 0.f;
        const float T30 = inv3 * (-e0 * inv0 - e1 * T10 - e2 * T20);
        const float T31 = inv3 * (-e1 * T11 - e2 * T21);
        const float T32 = inv3 * (-e2 * T22);
        const float T33 = inv3;

        const unsigned base = (blockIdx.x + (unsigned)it * GRID) * PAIR_B + goff;
        f8 o;
        o.a = comb4(v0.a, inv0); o.b = comb4(v0.b, inv0);
        stg256(ob + base, o);

        o.a = comb4(v0.a, T10, v1.a, T11); o.b = comb4(v0.b, T10, v1.b, T11);
        stg256(ob + base + MSTRIDE_B, o);

        o.a = comb4(v0.a, T20, v1.a, T21, v2.a, T22);
        o.b = comb4(v0.b, T20, v1.b, T21, v2.b, T22);
        stg256(ob + base + 2u * MSTRIDE_B, o);

        o.a = comb4(v0.a, T30, v1.a, T31, v2.a, T32, v3.a, T33);
        o.b = comb4(v0.b, T30, v1.b, T31, v2.b, T32, v3.b, T33);
        stg256(ob + base + 3u * MSTRIDE_B, o);
    }
}

extern "C" void kernel_launch(void* const* d_in, const int* in_sizes, int n_in,
                              void* d_out, int out_size) {
    const float* x = (const float*)d_in[0];
    float* out = (float*)d_out;
    gram_schmidt_kernel<<<GRID, NTHREADS>>>(x, out);
}

// round 14
// speedup vs baseline: 1.0909x; 1.0781x over previous
#include <cuda_runtime.h>
#include <cuda_bf16.h>

// Gram-Schmidt over M=4 model outputs, per (batch, channel) vector of D=1024.
// x: [4, 128, 64, 1024] fp32, out same shape.
//
// R2:  all 10 pairwise dots G_ij in ONE fused block reduction; GS coefficients
//      are scalar algebra on G (lower-triangular T, basis_i = sum_j T_ij v_j).
// R10: LDG.256/STG.256, 128 thr/CTA, grid 8192: kernel 37.2us, DRAM 70.6%.
//      (R3/R11/R13: all intra-CTA pipelining variants regressed -> closed.)
// R14: single-barrier reduction. Instead of bar -> 10-thread finalize -> bar,
//      every thread sums the 4 warp-partial rows itself from smem (broadcast
//      LDS.128, conflict-free) after ONE barrier. Removes a BAR.SYNC + the
//      serialized finalize stage from every CTA's critical path.

#define NTHREADS 128
#define D_DIM 1024
#define NPAIRS 8192              // B*C
#define MSTRIDE_B 33554432u      // B*C*D*4 bytes = 32 MB

struct f8 { float4 a, b; };

__device__ __forceinline__ f8 ldg256(const void* p) {
    f8 r;
    asm("ld.global.v8.b32 {%0,%1,%2,%3,%4,%5,%6,%7}, [%8];"
        : "=f"(r.a.x), "=f"(r.a.y), "=f"(r.a.z), "=f"(r.a.w),
          "=f"(r.b.x), "=f"(r.b.y), "=f"(r.b.z), "=f"(r.b.w)
        : "l"(p));
    return r;
}

__device__ __forceinline__ void stg256(void* p, f8 v) {
    asm volatile("st.global.v8.b32 [%0], {%1,%2,%3,%4,%5,%6,%7,%8};"
                 :: "l"(p),
                    "f"(v.a.x), "f"(v.a.y), "f"(v.a.z), "f"(v.a.w),
                    "f"(v.b.x), "f"(v.b.y), "f"(v.b.z), "f"(v.b.w)
                 : "memory");
}

__device__ __forceinline__ float dot8(f8 u, f8 v) {
    return u.a.x * v.a.x + u.a.y * v.a.y + u.a.z * v.a.z + u.a.w * v.a.w +
           u.b.x * v.b.x + u.b.y * v.b.y + u.b.z * v.b.z + u.b.w * v.b.w;
}

__device__ __forceinline__ float4 comb4(float4 v0, float s0) {
    return make_float4(s0 * v0.x, s0 * v0.y, s0 * v0.z, s0 * v0.w);
}
__device__ __forceinline__ float4 comb4(float4 v0, float s0, float4 v1, float s1) {
    return make_float4(s0 * v0.x + s1 * v1.x, s0 * v0.y + s1 * v1.y,
                       s0 * v0.z + s1 * v1.z, s0 * v0.w + s1 * v1.w);
}
__device__ __forceinline__ float4 comb4(float4 v0, float s0, float4 v1, float s1,
                                        float4 v2, float s2) {
    return make_float4(s0 * v0.x + s1 * v1.x + s2 * v2.x,
                       s0 * v0.y + s1 * v1.y + s2 * v2.y,
                       s0 * v0.z + s1 * v1.z + s2 * v2.z,
                       s0 * v0.w + s1 * v1.w + s2 * v2.w);
}
__device__ __forceinline__ float4 comb4(float4 v0, float s0, float4 v1, float s1,
                                        float4 v2, float s2, float4 v3, float s3) {
    return make_float4(s0 * v0.x + s1 * v1.x + s2 * v2.x + s3 * v3.x,
                       s0 * v0.y + s1 * v1.y + s2 * v2.y + s3 * v3.y,
                       s0 * v0.z + s1 * v1.z + s2 * v2.z + s3 * v3.z,
                       s0 * v0.w + s1 * v1.w + s2 * v2.w + s3 * v3.w);
}

__global__ __launch_bounds__(NTHREADS, 8)
void gram_schmidt_kernel(const float* __restrict__ x, float* __restrict__ out) {
    const int tid  = threadIdx.x;
    const int lane = tid & 31;
    const int warp = tid >> 5;          // 0..3

    // per-warp partials, 12-float rows (48B): [p0..p9, pad, pad]
    __shared__ __align__(16) float red[4][12];

    // byte offset: bc*4096 + tid*32, 32B-aligned, fits unsigned (max < 2^28).
    const unsigned base = blockIdx.x * (D_DIM * 4u) + (unsigned)tid * 32u;
    const char* xb = (const char*)x;
    char* ob = (char*)out;

    // 4 x LDG.256: 1KB contiguous per warp per instruction.
    f8 v0 = ldg256(xb + base);
    f8 v1 = ldg256(xb + base + MSTRIDE_B);
    f8 v2 = ldg256(xb + base + 2u * MSTRIDE_B);
    f8 v3 = ldg256(xb + base + 3u * MSTRIDE_B);

    // 10 pairwise dot partials: (00)(01)(02)(03)(11)(12)(13)(22)(23)(33)
    float p[10];
    p[0] = dot8(v0, v0); p[1] = dot8(v0, v1); p[2] = dot8(v0, v2);
    p[3] = dot8(v0, v3); p[4] = dot8(v1, v1); p[5] = dot8(v1, v2);
    p[6] = dot8(v1, v3); p[7] = dot8(v2, v2); p[8] = dot8(v2, v3);
    p[9] = dot8(v3, v3);

    // Warp butterfly: 10 values packed as 5 x 64-bit shuffles per level.
#pragma unroll
    for (int lvl = 16; lvl >= 1; lvl >>= 1) {
#pragma unroll
        for (int q = 0; q < 5; q++) {
            unsigned long long u =
                ((unsigned long long)__float_as_uint(p[2 * q + 1]) << 32) |
                (unsigned long long)__float_as_uint(p[2 * q]);
            unsigned long long r = __shfl_xor_sync(0xffffffffu, u, lvl);
            p[2 * q]     += __uint_as_float((unsigned)r);
            p[2 * q + 1] += __uint_as_float((unsigned)(r >> 32));
        }
    }

    if (lane == 0) {
        float4* row = reinterpret_cast<float4*>(red[warp]);
        row[0] = make_float4(p[0], p[1], p[2], p[3]);
        row[1] = make_float4(p[4], p[5], p[6], p[7]);
        red[warp][8] = p[8];
        red[warp][9] = p[9];
    }
    __syncthreads();   // the ONLY barrier

    // Every thread sums the 4 warp rows itself (broadcast LDS.128: same
    // address across the warp -> single wavefront each, conflict-free).
    float4 ga, gb;
    float g23, g33;
    {
        const float4* r0 = reinterpret_cast<const float4*>(red[0]);
        const float4* r1 = reinterpret_cast<const float4*>(red[1]);
        const float4* r2 = reinterpret_cast<const float4*>(red[2]);
        const float4* r3 = reinterpret_cast<const float4*>(red[3]);
        float4 a0 = r0[0], a1 = r1[0], a2 = r2[0], a3 = r3[0];
        float4 b0 = r0[1], b1 = r1[1], b2 = r2[1], b3 = r3[1];
        float4 c0 = r0[2], c1 = r1[2], c2 = r2[2], c3 = r3[2];
        ga.x = a0.x + a1.x + a2.x + a3.x;
        ga.y = a0.y + a1.y + a2.y + a3.y;
        ga.z = a0.z + a1.z + a2.z + a3.z;
        ga.w = a0.w + a1.w + a2.w + a3.w;
        gb.x = b0.x + b1.x + b2.x + b3.x;
        gb.y = b0.y + b1.y + b2.y + b3.y;
        gb.z = b0.z + b1.z + b2.z + b3.z;
        gb.w = b0.w + b1.w + b2.w + b3.w;
        g23  = c0.x + c1.x + c2.x + c3.x;
        g33  = c0.y + c1.y + c2.y + c3.y;
    }
    const float g00 = ga.x, g01 = ga.y, g02 = ga.z, g03 = ga.w;
    const float g11 = gb.x, g12 = gb.y, g13 = gb.z, g22 = gb.w;

    // ---- scalar GS recurrence on the Gram matrix (replicated per thread) ----
    const float inv0 = (g00 > 0.f) ? rsqrtf(g00) : 0.f;

    const float c0 = g01 * inv0;
    const float n1 = fmaxf(g11 - c0 * c0, 0.f);
    const float inv1 = (n1 > 0.f) ? rsqrtf(n1) : 0.f;
    const float T10 = -c0 * inv0 * inv1;
    const float T11 = inv1;

    const float d0 = g02 * inv0;
    const float d1 = T10 * g02 + T11 * g12;
    const float n2 = fmaxf(g22 - d0 * d0 - d1 * d1, 0.f);
    const float inv2 = (n2 > 0.f) ? rsqrtf(n2) : 0.f;
    const float T20 = inv2 * (-d0 * inv0 - d1 * T10);
    const float T21 = inv2 * (-d1 * T11);
    const float T22 = inv2;

    const float e0 = g03 * inv0;
    const float e1 = T10 * g03 + T11 * g13;
    const float e2 = T20 * g03 + T21 * g13 + T22 * g23;
    const float n3 = fmaxf(g33 - e0 * e0 - e1 * e1 - e2 * e2, 0.f);
    const float inv3 = (n3 > 0.f) ? rsqrtf(n3) : 0.f;
    const float T30 = inv3 * (-e0 * inv0 - e1 * T10 - e2 * T20);
    const float T31 = inv3 * (-e1 * T11 - e2 * T21);
    const float T32 = inv3 * (-e2 * T22);
    const float T33 = inv3;

    // ---- outputs: basis_i = sum_j T_ij v_j (4 x STG.256) ----
    f8 o;
    o.a = comb4(v0.a, inv0); o.b = comb4(v0.b, inv0);
    stg256(ob + base, o);

    o.a = comb4(v0.a, T10, v1.a, T11); o.b = comb4(v0.b, T10, v1.b, T11);
    stg256(ob + base + MSTRIDE_B, o);

    o.a = comb4(v0.a, T20, v1.a, T21, v2.a, T22);
    o.b = comb4(v0.b, T20, v1.b, T21, v2.b, T22);
    stg256(ob + base + 2u * MSTRIDE_B, o);

    o.a = comb4(v0.a, T30, v1.a, T31, v2.a, T32, v3.a, T33);
    o.b = comb4(v0.b, T30, v1.b, T31, v2.b, T32, v3.b, T33);
    stg256(ob + base + 3u * MSTRIDE_B, o);
}

extern "C" void kernel_launch(void* const* d_in, const int* in_sizes, int n_in,
                              void* d_out, int out_size) {
    const float* x = (const float*)d_in[0];
    float* out = (float*)d_out;
    gram_schmidt_kernel<<<NPAIRS, NTHREADS>>>(x, out);
}